// round 3
// baseline (speedup 1.0000x reference)
#include <cuda_runtime.h>

#define BN   8
#define NP   2048
#define DETK 100
#define NT   512
#define NW   (NT / 32)    // 16 warps
#define EPT  (NP / NT)    // 4 original elements per thread
#define FULL 0xffffffffu

static __device__ __forceinline__ float stable_sigmoid(float d) {
    return (d >= 0.0f) ? (1.0f / (1.0f + expf(-d)))
                       : (expf(d) / (1.0f + expf(d)));
}
static __device__ __forceinline__ unsigned f2s(float f) {
    unsigned u = __float_as_uint(f);
    return (u & 0x80000000u) ? ~u : (u | 0x80000000u);
}
static __device__ __forceinline__ float s2f(unsigned u) {
    u = (u & 0x80000000u) ? (u & 0x7FFFFFFFu) : ~u;
    return __uint_as_float(u);
}

struct Smem {
    float4   cbox[NP];        // compacted boxes (orig-index order)  32 KB
    unsigned ckey[NP];        // compacted score keys                 8 KB
    int      wcnt[NW];        // per-warp valid counts (compaction)
    unsigned pkey[2][NW];     // double-buffered per-warp max key
    unsigned pslot[2][NW];    // double-buffered per-warp min slot
    int      keep[DETK];      // kept compacted slots, keep order
    unsigned keepkey[DETK];   // their score keys
};

__global__ __launch_bounds__(NT, 1)
void seas_postprocess_kernel(const float* __restrict__ clss,   // [B,N,2]
                             const float* __restrict__ regs,   // [B,N,4]
                             const float* __restrict__ qlts,   // [B,N,1]
                             const float* __restrict__ props,  // [B,N,4]
                             float* __restrict__ out)
{
    __shared__ Smem sm;

    const int b    = blockIdx.x;
    const int tid  = threadIdx.x;
    const int w    = tid >> 5;
    const int lane = tid & 31;

    const float W_IMG = 1344.0f, H_IMG = 800.0f;
    const float CLIPV = 4.135166556742356f;  // log(1000/16)
    const float NMS_T = 0.4f;

    const float2* cls = (const float2*)(clss  + (size_t)b * NP * 2);
    const float4* reg = (const float4*)(regs  + (size_t)b * NP * 4);
    const float*  qlt =                 qlts  + (size_t)b * NP;
    const float4* prp = (const float4*)(props + (size_t)b * NP * 4);

    // ---- Phase 1: decode/clip/score EPT consecutive proposals per thread ----
    float4   pb[EPT];
    unsigned pk[EPT];
    int      nvalid = 0;
    #pragma unroll
    for (int e = 0; e < EPT; ++e) {
        int j = tid * EPT + e;
        float4 p = prp[j];
        float bw = p.z - p.x, bh = p.w - p.y;
        float cx = p.x + 0.5f * bw, cy = p.y + 0.5f * bh;

        float4 r = reg[j];
        float dx = r.x * 0.1f;
        float dy = r.y * 0.1f;
        float dw = fminf(r.z * 0.2f, CLIPV);
        float dh = fminf(r.w * 0.2f, CLIPV);

        float pcx = dx * bw + cx;
        float pcy = dy * bh + cy;
        float pw  = expf(dw) * bw;
        float ph  = expf(dh) * bh;

        float x1 = fminf(fmaxf(pcx - 0.5f * pw, 0.0f), W_IMG);
        float y1 = fminf(fmaxf(pcy - 0.5f * ph, 0.0f), H_IMG);
        float x2 = fminf(fmaxf(pcx + 0.5f * pw, 0.0f), W_IMG);
        float y2 = fminf(fmaxf(pcy + 0.5f * ph, 0.0f), H_IMG);

        bool small_keep = ((x2 - x1) >= 0.01f) && ((y2 - y1) >= 0.01f);

        float2 c = cls[j];
        float raw = stable_sigmoid(c.y - c.x);        // softmax fg prob (C=2)
        bool  score_keep = raw > 0.5f;
        float score = stable_sigmoid(qlt[j]) * raw;   // quality-weighted

        bool valid = small_keep && score_keep;
        pb[e] = make_float4(x1, y1, x2, y2);
        pk[e] = valid ? f2s(score) : 0u;              // valid <=> key >= 0x80000000
        nvalid += valid ? 1 : 0;
    }

    // ---- Phase 2: order-preserving compaction (slot order == original order) ----
    {
        int inc = nvalid;
        #pragma unroll
        for (int d = 1; d < 32; d <<= 1) {
            int t = __shfl_up_sync(FULL, inc, d);
            if (lane >= d) inc += t;
        }
        if (lane == 31) sm.wcnt[w] = inc;
        int excl = inc - nvalid;
        __syncthreads();
        int base = 0;
        #pragma unroll
        for (int i = 0; i < NW; ++i) base += (i < w) ? sm.wcnt[i] : 0;
        int idx = base + excl;
        #pragma unroll
        for (int e = 0; e < EPT; ++e) {
            if (pk[e] != 0u) {
                sm.cbox[idx] = pb[e];
                sm.ckey[idx] = pk[e];
                idx++;
            }
        }
    }
    __syncthreads();

    int V = 0;
    #pragma unroll
    for (int i = 0; i < NW; ++i) V += sm.wcnt[i];
    const int ne_act = (V + NT - 1) / NT;   // uniform across block (<= EPT)

    // ---- Phase 3: load my strided slots into registers ----
    float4   myb[EPT];
    float    mya[EPT];
    unsigned mykey[EPT];
    #pragma unroll
    for (int e = 0; e < EPT; ++e) mykey[e] = 0u;
    for (int e = 0; e < ne_act; ++e) {
        int slot = e * NT + tid;
        if (slot < V) {
            float4 bx = sm.cbox[slot];
            myb[e]   = bx;
            mya[e]   = (bx.z - bx.x) * (bx.w - bx.y);
            mykey[e] = sm.ckey[slot];
        }
    }

    // ---- Phase 4: greedy NMS, one barrier per iteration ----
    int cnt = 0;
    int parity = 0;
    while (true) {
        // per-thread argmax (ties -> smallest slot, since e ascending & strict >)
        unsigned lk = 0u, lslot = 0xFFFFFFFFu;
        for (int e = 0; e < ne_act; ++e) {
            if (mykey[e] > lk) { lk = mykey[e]; lslot = (unsigned)(e * NT + tid); }
        }
        unsigned gk   = __reduce_max_sync(FULL, lk);
        unsigned cand = (lk == gk) ? lslot : 0xFFFFFFFFu;
        unsigned gs   = __reduce_min_sync(FULL, cand);
        if (lane == 0) { sm.pkey[parity][w] = gk; sm.pslot[parity][w] = gs; }
        __syncthreads();

        // every warp redundantly reduces the 16 partials -> no 2nd barrier
        unsigned k2 = (lane < NW) ? sm.pkey[parity][lane]  : 0u;
        unsigned s2 = (lane < NW) ? sm.pslot[parity][lane] : 0xFFFFFFFFu;
        unsigned gk2   = __reduce_max_sync(FULL, k2);
        unsigned cand2 = (k2 == gk2) ? s2 : 0xFFFFFFFFu;
        unsigned gs2   = __reduce_min_sync(FULL, cand2);
        parity ^= 1;

        if (gk2 < 0x80000000u) break;        // no valid candidate left
        if (tid == 0) { sm.keep[cnt] = (int)gs2; sm.keepkey[cnt] = gk2; }
        cnt++;

        // suppress against the selected box (self suppressed via IoU==1 + slot check)
        float4 bi = sm.cbox[gs2];
        float  ai = (bi.z - bi.x) * (bi.w - bi.y);
        for (int e = 0; e < ne_act; ++e) {
            float iw = fmaxf(fminf(bi.z, myb[e].z) - fmaxf(bi.x, myb[e].x), 0.0f);
            float ih = fmaxf(fminf(bi.w, myb[e].w) - fmaxf(bi.y, myb[e].y), 0.0f);
            float inter = iw * ih;
            float iou = inter / (ai + mya[e] - inter + 1e-9f);
            if (iou > NMS_T || (unsigned)(e * NT + tid) == gs2) mykey[e] = 0u;
        }
        if (cnt >= DETK) break;
    }
    __syncthreads();

    // ---- Phase 5: outputs [boxes 3200 | scores 800 | classes 800 | valid 800] ----
    if (tid < DETK) {
        int k = tid;
        float4 ob = make_float4(0.f, 0.f, 0.f, 0.f);
        float os = 0.f, oc = 0.f, ov = 0.f;
        if (k < cnt) {
            ob = sm.cbox[sm.keep[k]];
            os = s2f(sm.keepkey[k]);
            oc = 1.0f;
            ov = 1.0f;
        }
        float* obp = out + ((size_t)b * DETK + k) * 4;
        obp[0] = ob.x; obp[1] = ob.y; obp[2] = ob.z; obp[3] = ob.w;
        const int SB = BN * DETK * 4;   // 3200
        const int SC = BN * DETK;       // 800
        out[SB +          b * DETK + k] = os;
        out[SB + SC +     b * DETK + k] = oc;
        out[SB + 2 * SC + b * DETK + k] = ov;
    }
}

extern "C" void kernel_launch(void* const* d_in, const int* in_sizes, int n_in,
                              void* d_out, int out_size) {
    const float* clss  = (const float*)d_in[0];  // [8,2048,2]
    const float* regs  = (const float*)d_in[1];  // [8,2048,4]
    const float* qlts  = (const float*)d_in[2];  // [8,2048,1]
    const float* props = (const float*)d_in[3];  // [8,2048,4]
    float* out = (float*)d_out;

    seas_postprocess_kernel<<<BN, NT>>>(clss, regs, qlts, props, out);
}

// round 4
// speedup vs baseline: 2.5400x; 2.5400x over previous
#include <cuda_runtime.h>

#define BN   8
#define NP   2048
#define DETK 100
#define NT   1024
#define NW   (NT / 32)    // 32 warps
#define EPT  (NP / NT)    // 2 consecutive proposals per thread (decode phase)
#define FULL 0xffffffffu

static __device__ __forceinline__ float stable_sigmoid(float d) {
    return (d >= 0.0f) ? (1.0f / (1.0f + expf(-d)))
                       : (expf(d) / (1.0f + expf(d)));
}
static __device__ __forceinline__ unsigned f2s(float f) {
    unsigned u = __float_as_uint(f);
    return (u & 0x80000000u) ? ~u : (u | 0x80000000u);
}
static __device__ __forceinline__ float s2f(unsigned u) {
    u = (u & 0x80000000u) ? (u & 0x7FFFFFFFu) : ~u;
    return __uint_as_float(u);
}

struct Smem {
    float4   cbox[NP];        // compacted boxes, original-index order (32 KB)
    unsigned ckey[NP];        // compacted score keys (8 KB)
    int      wcnt[NW];        // per-warp valid counts
    unsigned pkey[NW];        // per-warp max key
    unsigned pslot[NW];       // per-warp min slot at that key
    int      keep[DETK];
    unsigned keepkey[DETK];
    int      sel;
};

__global__ __launch_bounds__(NT, 1)
void seas_postprocess_kernel(const float* __restrict__ clss,
                             const float* __restrict__ regs,
                             const float* __restrict__ qlts,
                             const float* __restrict__ props,
                             float* __restrict__ out)
{
    __shared__ Smem sm;

    const int b    = blockIdx.x;
    const int tid  = threadIdx.x;
    const int w    = tid >> 5;
    const int lane = tid & 31;

    const float W_IMG = 1344.0f, H_IMG = 800.0f;
    const float CLIPV = 4.135166556742356f;  // log(1000/16)

    const float2* cls = (const float2*)(clss  + (size_t)b * NP * 2);
    const float4* reg = (const float4*)(regs  + (size_t)b * NP * 4);
    const float*  qlt =                 qlts  + (size_t)b * NP;
    const float4* prp = (const float4*)(props + (size_t)b * NP * 4);

    // ---- Phase 1: decode/clip/score 2 consecutive proposals per thread ----
    float4   pb[EPT];
    unsigned pk[EPT];
    int      nvalid = 0;
    #pragma unroll
    for (int e = 0; e < EPT; ++e) {
        int j = tid * EPT + e;                 // consecutive -> order-preserving compaction
        float4 p = prp[j];
        float bw = p.z - p.x, bh = p.w - p.y;
        float cx = p.x + 0.5f * bw, cy = p.y + 0.5f * bh;

        float4 r = reg[j];
        float dx = r.x * 0.1f;
        float dy = r.y * 0.1f;
        float dw = fminf(r.z * 0.2f, CLIPV);
        float dh = fminf(r.w * 0.2f, CLIPV);

        float pcx = dx * bw + cx;
        float pcy = dy * bh + cy;
        float pw  = expf(dw) * bw;
        float ph  = expf(dh) * bh;

        float x1 = fminf(fmaxf(pcx - 0.5f * pw, 0.0f), W_IMG);
        float y1 = fminf(fmaxf(pcy - 0.5f * ph, 0.0f), H_IMG);
        float x2 = fminf(fmaxf(pcx + 0.5f * pw, 0.0f), W_IMG);
        float y2 = fminf(fmaxf(pcy + 0.5f * ph, 0.0f), H_IMG);

        bool small_keep = ((x2 - x1) >= 0.01f) && ((y2 - y1) >= 0.01f);

        float2 c = cls[j];
        float raw = stable_sigmoid(c.y - c.x);
        bool  score_keep = raw > 0.5f;
        float score = stable_sigmoid(qlt[j]) * raw;

        bool valid = small_keep && score_keep;
        pb[e] = make_float4(x1, y1, x2, y2);
        pk[e] = valid ? f2s(score) : 0u;       // valid <=> key >= 0x80000000
        nvalid += valid ? 1 : 0;
    }

    // ---- Phase 2: order-preserving compaction into smem ----
    {
        int inc = nvalid;
        #pragma unroll
        for (int d = 1; d < 32; d <<= 1) {
            int t = __shfl_up_sync(FULL, inc, d);
            if (lane >= d) inc += t;
        }
        if (lane == 31) sm.wcnt[w] = inc;
        int excl = inc - nvalid;
        __syncthreads();
        int base = 0;
        #pragma unroll
        for (int i = 0; i < NW; ++i) base += (i < w) ? sm.wcnt[i] : 0;
        int idx = base + excl;
        #pragma unroll
        for (int e = 0; e < EPT; ++e) {
            if (pk[e] != 0u) {
                sm.cbox[idx] = pb[e];
                sm.ckey[idx] = pk[e];
                idx++;
            }
        }
    }
    __syncthreads();

    int V = 0;
    #pragma unroll
    for (int i = 0; i < NW; ++i) V += sm.wcnt[i];

    // ---- Phase 3: each thread owns slot tid (and rarely slot NT+tid) ----
    float4   b0 = make_float4(0.f, 0.f, 0.f, 0.f);
    float    a0p = 1e-9f;                       // area + 1e-9
    unsigned k0 = 0u;
    if (tid < V) {
        b0  = sm.cbox[tid];
        a0p = (b0.z - b0.x) * (b0.w - b0.y) + 1e-9f;
        k0  = sm.ckey[tid];
    }
    float4   b1 = make_float4(0.f, 0.f, 0.f, 0.f);
    float    a1p = 1e-9f;
    unsigned k1 = 0u;
    const bool has2 = (NT + tid) < V;           // true for at most V-1024 threads
    if (has2) {
        b1  = sm.cbox[NT + tid];
        a1p = (b1.z - b1.x) * (b1.w - b1.y) + 1e-9f;
        k1  = sm.ckey[NT + tid];
    }

    // ---- Phase 4: greedy NMS, fused argmax selection ----
    int cnt = 0;
    while (true) {
        // local pick (prefer slot tid on ties -> min-slot tie-break overall)
        unsigned lk = k0, ls = (unsigned)tid;
        if (k1 > k0) { lk = k1; ls = (unsigned)(NT + tid); }

        unsigned gk   = __reduce_max_sync(FULL, lk);
        unsigned cand = (lk == gk) ? ls : 0xFFFFFFFFu;
        unsigned gs   = __reduce_min_sync(FULL, cand);
        if (lane == 0) { sm.pkey[w] = gk; sm.pslot[w] = gs; }
        __syncthreads();

        if (w == 0) {
            unsigned k2 = sm.pkey[lane];
            unsigned s2 = sm.pslot[lane];
            unsigned gk2   = __reduce_max_sync(FULL, k2);
            unsigned cand2 = (k2 == gk2) ? s2 : 0xFFFFFFFFu;
            unsigned gs2   = __reduce_min_sync(FULL, cand2);
            if (lane == 0) {
                if (gk2 >= 0x80000000u) {
                    sm.keep[cnt]    = (int)gs2;
                    sm.keepkey[cnt] = gk2;
                    sm.sel          = (int)gs2;
                } else {
                    sm.sel = -1;
                }
            }
        }
        __syncthreads();

        int sel = sm.sel;
        if (sel < 0) break;
        cnt++;

        float4 bi = sm.cbox[sel];
        float  ai = (bi.z - bi.x) * (bi.w - bi.y);

        // iou > 0.4  <=>  3.5*inter > ai + aj + 1e-9
        {
            float iw = fmaxf(fminf(bi.z, b0.z) - fmaxf(bi.x, b0.x), 0.0f);
            float ih = fmaxf(fminf(bi.w, b0.w) - fmaxf(bi.y, b0.y), 0.0f);
            float inter = iw * ih;
            if (3.5f * inter > ai + a0p || tid == sel) k0 = 0u;
        }
        if (has2) {
            float iw = fmaxf(fminf(bi.z, b1.z) - fmaxf(bi.x, b1.x), 0.0f);
            float ih = fmaxf(fminf(bi.w, b1.w) - fmaxf(bi.y, b1.y), 0.0f);
            float inter = iw * ih;
            if (3.5f * inter > ai + a1p || (NT + tid) == sel) k1 = 0u;
        }
        if (cnt >= DETK) break;
    }
    __syncthreads();

    // ---- Phase 5: outputs [boxes 3200 | scores 800 | classes 800 | valid 800] ----
    if (tid < DETK) {
        int k = tid;
        float4 ob = make_float4(0.f, 0.f, 0.f, 0.f);
        float os = 0.f, oc = 0.f, ov = 0.f;
        if (k < cnt) {
            ob = sm.cbox[sm.keep[k]];
            os = s2f(sm.keepkey[k]);
            oc = 1.0f;
            ov = 1.0f;
        }
        float* obp = out + ((size_t)b * DETK + k) * 4;
        obp[0] = ob.x; obp[1] = ob.y; obp[2] = ob.z; obp[3] = ob.w;
        const int SB = BN * DETK * 4;   // 3200
        const int SC = BN * DETK;       // 800
        out[SB +          b * DETK + k] = os;
        out[SB + SC +     b * DETK + k] = oc;
        out[SB + 2 * SC + b * DETK + k] = ov;
    }
}

extern "C" void kernel_launch(void* const* d_in, const int* in_sizes, int n_in,
                              void* d_out, int out_size) {
    const float* clss  = (const float*)d_in[0];
    const float* regs  = (const float*)d_in[1];
    const float* qlts  = (const float*)d_in[2];
    const float* props = (const float*)d_in[3];
    float* out = (float*)d_out;

    seas_postprocess_kernel<<<BN, NT>>>(clss, regs, qlts, props, out);
}

// round 5
// speedup vs baseline: 3.3918x; 1.3354x over previous
#include <cuda_runtime.h>

#define BN   8
#define NP   2048
#define DETK 100
#define NT   1024
#define FULL 0xffffffffu

static __device__ __forceinline__ float stable_sigmoid(float d) {
    return (d >= 0.0f) ? (1.0f / (1.0f + expf(-d)))
                       : (expf(d) / (1.0f + expf(d)));
}
static __device__ __forceinline__ unsigned f2s(float f) {
    unsigned u = __float_as_uint(f);
    return (u & 0x80000000u) ? ~u : (u | 0x80000000u);
}
static __device__ __forceinline__ float s2f(unsigned u) {
    u = (u & 0x80000000u) ? (u & 0x7FFFFFFFu) : ~u;
    return __uint_as_float(u);
}

struct Smem {
    float4             sbox[NP];      // decoded+clipped boxes, original order (32 KB)
    unsigned long long skeys[NP];     // sort keys [score_sortable:32 | NP-1-j:32] (16 KB)
    float4             kbox[DETK];    // kept boxes in keep order
    float              karea[DETK];   // their raw areas
    unsigned           keepkey[DETK]; // their score keys
    int                cnt;
};

__global__ __launch_bounds__(NT, 1)
void seas_postprocess_kernel(const float* __restrict__ clss,
                             const float* __restrict__ regs,
                             const float* __restrict__ qlts,
                             const float* __restrict__ props,
                             float* __restrict__ out)
{
    extern __shared__ unsigned char smem_raw[];
    Smem& sm = *reinterpret_cast<Smem*>(smem_raw);

    const int b    = blockIdx.x;
    const int tid  = threadIdx.x;
    const int w    = tid >> 5;
    const int lane = tid & 31;

    const float W_IMG = 1344.0f, H_IMG = 800.0f;
    const float CLIPV = 4.135166556742356f;  // log(1000/16)

    const float2* cls = (const float2*)(clss  + (size_t)b * NP * 2);
    const float4* reg = (const float4*)(regs  + (size_t)b * NP * 4);
    const float*  qlt =                 qlts  + (size_t)b * NP;
    const float4* prp = (const float4*)(props + (size_t)b * NP * 4);

    // ---- Phase 1: decode, clip, score ----
    #pragma unroll
    for (int e = 0; e < NP / NT; ++e) {
        int j = e * NT + tid;
        float4 p = prp[j];
        float bw = p.z - p.x, bh = p.w - p.y;
        float cx = p.x + 0.5f * bw, cy = p.y + 0.5f * bh;

        float4 r = reg[j];
        float dx = r.x * 0.1f;
        float dy = r.y * 0.1f;
        float dw = fminf(r.z * 0.2f, CLIPV);
        float dh = fminf(r.w * 0.2f, CLIPV);

        float pcx = dx * bw + cx;
        float pcy = dy * bh + cy;
        float pw  = expf(dw) * bw;
        float ph  = expf(dh) * bh;

        float x1 = fminf(fmaxf(pcx - 0.5f * pw, 0.0f), W_IMG);
        float y1 = fminf(fmaxf(pcy - 0.5f * ph, 0.0f), H_IMG);
        float x2 = fminf(fmaxf(pcx + 0.5f * pw, 0.0f), W_IMG);
        float y2 = fminf(fmaxf(pcy + 0.5f * ph, 0.0f), H_IMG);

        bool small_keep = ((x2 - x1) >= 0.01f) && ((y2 - y1) >= 0.01f);

        float2 c = cls[j];
        float raw = stable_sigmoid(c.y - c.x);
        bool  score_keep = raw > 0.5f;
        float score = stable_sigmoid(qlt[j]) * raw;

        bool valid = small_keep && score_keep;
        unsigned k32 = valid ? f2s(score) : 0u;   // valid <=> k32 >= 0x80000000

        sm.sbox[j]  = make_float4(x1, y1, x2, y2);
        sm.skeys[j] = ((unsigned long long)k32 << 32) | (unsigned)(NP - 1 - j);
    }
    if (tid == 0) sm.cnt = 0;
    __syncthreads();

    // ---- Phase 2: bitonic sort descending, 1 compare-exchange per thread/stage ----
    for (int k = 2; k <= NP; k <<= 1) {
        for (int jj = k >> 1; jj > 0; jj >>= 1) {
            int i = 2 * tid - (tid & (jj - 1));   // jj-bit of i is 0; partner = i + jj
            unsigned long long a = sm.skeys[i];
            unsigned long long c = sm.skeys[i + jj];
            bool asc = (i & k) != 0;              // final pass: descending
            bool sw  = asc ? (a > c) : (a < c);
            if (sw) { sm.skeys[i] = c; sm.skeys[i + jj] = a; }
            __syncthreads();
        }
    }

    // ---- Phase 3: single-warp windowed greedy NMS (no block barriers) ----
    if (w == 0) {
        int cnt = 0;
        for (int p = 0; p < NP && cnt < DETK; p += 32) {
            int c = p + lane;
            unsigned long long key = sm.skeys[c];
            unsigned k32 = (unsigned)(key >> 32);
            bool valid = k32 >= 0x80000000u;
            unsigned vm = __ballot_sync(FULL, valid);
            if (vm == 0) break;                   // sorted: all later are invalid too

            int orig = NP - 1 - (int)(unsigned)key;
            float4 bx = sm.sbox[orig];
            float  ar = (bx.z - bx.x) * (bx.w - bx.y);
            float  ap = ar + 1e-9f;

            // test candidate vs all existing keeps (broadcast smem reads)
            bool sup = false;
            for (int t = 0; t < cnt; ++t) {
                float4 kb = sm.kbox[t];
                float  ka = sm.karea[t];
                float iw = fmaxf(fminf(kb.z, bx.z) - fmaxf(kb.x, bx.x), 0.0f);
                float ih = fmaxf(fminf(kb.w, bx.w) - fmaxf(kb.y, bx.y), 0.0f);
                float inter = iw * ih;
                sup = sup || (3.5f * inter > ka + ap);   // iou > 0.4
            }

            // sequential-in-warp greedy over the 32 window candidates
            #pragma unroll 1
            for (int i2 = 0; i2 < 32; ++i2) {
                bool ival = __shfl_sync(FULL, valid, i2);
                bool isup = __shfl_sync(FULL, sup, i2);
                if (ival && !isup) {
                    float kx1 = __shfl_sync(FULL, bx.x, i2);
                    float ky1 = __shfl_sync(FULL, bx.y, i2);
                    float kx2 = __shfl_sync(FULL, bx.z, i2);
                    float ky2 = __shfl_sync(FULL, bx.w, i2);
                    float ka  = __shfl_sync(FULL, ar, i2);
                    if (lane > i2) {
                        float iw = fmaxf(fminf(kx2, bx.z) - fmaxf(kx1, bx.x), 0.0f);
                        float ih = fmaxf(fminf(ky2, bx.w) - fmaxf(ky1, bx.y), 0.0f);
                        float inter = iw * ih;
                        sup = sup || (3.5f * inter > ka + ap);
                    }
                    if (lane == i2) {
                        sm.kbox[cnt]    = bx;
                        sm.karea[cnt]   = ar;
                        sm.keepkey[cnt] = k32;
                    }
                    cnt++;
                    if (cnt >= DETK) break;
                }
            }
        }
        if (lane == 0) sm.cnt = cnt;
    }
    __syncthreads();

    // ---- Phase 4: outputs [boxes 3200 | scores 800 | classes 800 | valid 800] ----
    if (tid < DETK) {
        int k = tid;
        float4 ob = make_float4(0.f, 0.f, 0.f, 0.f);
        float os = 0.f, oc = 0.f, ov = 0.f;
        if (k < sm.cnt) {
            ob = sm.kbox[k];
            os = s2f(sm.keepkey[k]);
            oc = 1.0f;
            ov = 1.0f;
        }
        float* obp = out + ((size_t)b * DETK + k) * 4;
        obp[0] = ob.x; obp[1] = ob.y; obp[2] = ob.z; obp[3] = ob.w;
        const int SB = BN * DETK * 4;   // 3200
        const int SC = BN * DETK;       // 800
        out[SB +          b * DETK + k] = os;
        out[SB + SC +     b * DETK + k] = oc;
        out[SB + 2 * SC + b * DETK + k] = ov;
    }
}

extern "C" void kernel_launch(void* const* d_in, const int* in_sizes, int n_in,
                              void* d_out, int out_size) {
    const float* clss  = (const float*)d_in[0];
    const float* regs  = (const float*)d_in[1];
    const float* qlts  = (const float*)d_in[2];
    const float* props = (const float*)d_in[3];
    float* out = (float*)d_out;

    size_t smem = sizeof(Smem);
    cudaFuncSetAttribute(seas_postprocess_kernel,
                         cudaFuncAttributeMaxDynamicSharedMemorySize, (int)smem);
    seas_postprocess_kernel<<<BN, NT, smem>>>(clss, regs, qlts, props, out);
}

// round 6
// speedup vs baseline: 4.3426x; 1.2803x over previous
#include <cuda_runtime.h>

#define BN   8
#define NP   2048
#define DETK 100
#define NT   1024
#define FULL 0xffffffffu

static __device__ __forceinline__ float stable_sigmoid(float d) {
    return (d >= 0.0f) ? (1.0f / (1.0f + expf(-d)))
                       : (expf(d) / (1.0f + expf(d)));
}
static __device__ __forceinline__ unsigned f2s(float f) {
    unsigned u = __float_as_uint(f);
    return (u & 0x80000000u) ? ~u : (u | 0x80000000u);
}
static __device__ __forceinline__ float s2f(unsigned u) {
    u = (u & 0x80000000u) ? (u & 0x7FFFFFFFu) : ~u;
    return __uint_as_float(u);
}

struct Smem {
    float4             sbox[NP];       // decoded+clipped boxes, original order (32 KB)
    float4             kbox[DETK];     // kept boxes, keep order
    float4             swbox[32];      // window scratch boxes
    unsigned long long kbuf[2][NP];    // sort exchange buffers (32 KB)
    float              karea[DETK];
    unsigned           keepkey[DETK];
    float              swarea[32];
    int                cnt;
};

__global__ __launch_bounds__(NT, 1)
void seas_postprocess_kernel(const float* __restrict__ clss,
                             const float* __restrict__ regs,
                             const float* __restrict__ qlts,
                             const float* __restrict__ props,
                             float* __restrict__ out)
{
    extern __shared__ unsigned char smem_raw[];
    Smem& sm = *reinterpret_cast<Smem*>(smem_raw);

    const int b    = blockIdx.x;
    const int tid  = threadIdx.x;
    const int w    = tid >> 5;
    const int lane = tid & 31;

    const float W_IMG = 1344.0f, H_IMG = 800.0f;
    const float CLIPV = 4.135166556742356f;  // log(1000/16)

    const float2* cls = (const float2*)(clss  + (size_t)b * NP * 2);
    const float4* reg = (const float4*)(regs  + (size_t)b * NP * 4);
    const float*  qlt =                 qlts  + (size_t)b * NP;
    const float4* prp = (const float4*)(props + (size_t)b * NP * 4);

    // ---- Phase 1: decode, clip, score; keys stay in registers ----
    unsigned long long ekey[2];
    #pragma unroll
    for (int e = 0; e < 2; ++e) {
        int j = e * NT + tid;
        float4 p = prp[j];
        float bw = p.z - p.x, bh = p.w - p.y;
        float cx = p.x + 0.5f * bw, cy = p.y + 0.5f * bh;

        float4 r = reg[j];
        float dx = r.x * 0.1f;
        float dy = r.y * 0.1f;
        float dw = fminf(r.z * 0.2f, CLIPV);
        float dh = fminf(r.w * 0.2f, CLIPV);

        float pcx = dx * bw + cx;
        float pcy = dy * bh + cy;
        float pw  = expf(dw) * bw;
        float ph  = expf(dh) * bh;

        float x1 = fminf(fmaxf(pcx - 0.5f * pw, 0.0f), W_IMG);
        float y1 = fminf(fmaxf(pcy - 0.5f * ph, 0.0f), H_IMG);
        float x2 = fminf(fmaxf(pcx + 0.5f * pw, 0.0f), W_IMG);
        float y2 = fminf(fmaxf(pcy + 0.5f * ph, 0.0f), H_IMG);

        bool small_keep = ((x2 - x1) >= 0.01f) && ((y2 - y1) >= 0.01f);

        float2 c = cls[j];
        float raw = stable_sigmoid(c.y - c.x);
        bool  score_keep = raw > 0.5f;
        float score = stable_sigmoid(qlt[j]) * raw;

        bool valid = small_keep && score_keep;
        unsigned k32 = valid ? f2s(score) : 0u;   // valid <=> k32 >= 0x80000000

        sm.sbox[j] = make_float4(x1, y1, x2, y2);
        ekey[e] = ((unsigned long long)k32 << 32) | (unsigned)(NP - 1 - j);
    }
    if (tid == 0) sm.cnt = 0;
    // NOTE: no barrier needed yet; first sort stages are register/shfl only.

    // ---- Phase 2: hybrid bitonic sort, descending ----
    // element idx0 = tid, idx1 = tid + 1024. takemax = ((idx&k)==0) != ((idx&jj)!=0)
    int cur = 0;
    #pragma unroll
    for (int k = 2; k <= NP; k <<= 1) {
        #pragma unroll
        for (int jj = k >> 1; jj > 0; jj >>= 1) {
            if (jj == 1024) {
                // k==2048 only: idx0 lower+desc -> max; idx1 -> min
                unsigned long long mx = ekey[0] > ekey[1] ? ekey[0] : ekey[1];
                unsigned long long mn = ekey[0] > ekey[1] ? ekey[1] : ekey[0];
                ekey[0] = mx; ekey[1] = mn;
            } else if (jj >= 32) {
                sm.kbuf[cur][tid]      = ekey[0];
                sm.kbuf[cur][tid + NT] = ekey[1];
                __syncthreads();
                unsigned long long p0 = sm.kbuf[cur][tid ^ jj];
                unsigned long long p1 = sm.kbuf[cur][(tid + NT) ^ jj];
                bool up = (tid & jj) != 0;                 // same for both elements (jj<1024)
                bool tm0 = ((tid & k) == 0) != up;
                bool tm1 = (((tid + NT) & k) == 0) != up;
                ekey[0] = tm0 ? (ekey[0] > p0 ? ekey[0] : p0) : (ekey[0] < p0 ? ekey[0] : p0);
                ekey[1] = tm1 ? (ekey[1] > p1 ? ekey[1] : p1) : (ekey[1] < p1 ? ekey[1] : p1);
                cur ^= 1;
            } else {
                unsigned long long p0 = __shfl_xor_sync(FULL, ekey[0], jj);
                unsigned long long p1 = __shfl_xor_sync(FULL, ekey[1], jj);
                bool up = (lane & jj) != 0;
                bool tm0 = ((tid & k) == 0) != up;
                bool tm1 = (((tid + NT) & k) == 0) != up;
                ekey[0] = tm0 ? (ekey[0] > p0 ? ekey[0] : p0) : (ekey[0] < p0 ? ekey[0] : p0);
                ekey[1] = tm1 ? (ekey[1] > p1 ? ekey[1] : p1) : (ekey[1] < p1 ? ekey[1] : p1);
            }
        }
    }
    // publish sorted keys
    sm.kbuf[cur][tid]      = ekey[0];
    sm.kbuf[cur][tid + NT] = ekey[1];
    __syncthreads();
    const unsigned long long* kk = sm.kbuf[cur];

    // ---- Phase 3: single-warp windowed greedy NMS ----
    if (w == 0) {
        int cnt = 0;
        for (int p = 0; p < NP && cnt < DETK; p += 32) {
            unsigned long long key = kk[p + lane];
            unsigned k32 = (unsigned)(key >> 32);
            bool valid = k32 >= 0x80000000u;
            if (__ballot_sync(FULL, valid) == 0) break;  // sorted: rest invalid

            int orig = NP - 1 - (int)(unsigned)key;
            float4 bx = sm.sbox[orig];
            float  ar = (bx.z - bx.x) * (bx.w - bx.y);
            float  ap = ar + 1e-9f;

            // vs previously kept boxes
            bool sup = false;
            #pragma unroll 4
            for (int t = 0; t < cnt; ++t) {
                float4 kb = sm.kbox[t];
                float  ka = sm.karea[t];
                float iw = fmaxf(fminf(kb.z, bx.z) - fmaxf(kb.x, bx.x), 0.0f);
                float ih = fmaxf(fminf(kb.w, bx.w) - fmaxf(kb.y, bx.y), 0.0f);
                sup = sup || (3.5f * (iw * ih) > ka + ap);   // iou > 0.4
            }

            // build intra-window suppression mask (bits i < lane only)
            sm.swbox[lane]  = bx;
            sm.swarea[lane] = ar;
            __syncwarp();
            unsigned supmask = 0u;
            #pragma unroll 8
            for (int i = 0; i < 32; ++i) {
                float4 b2 = sm.swbox[i];
                float  a2 = sm.swarea[i];
                float iw = fmaxf(fminf(b2.z, bx.z) - fmaxf(b2.x, bx.x), 0.0f);
                float ih = fmaxf(fminf(b2.w, bx.w) - fmaxf(b2.y, bx.y), 0.0f);
                bool s = (3.5f * (iw * ih) > a2 + ap) && (i < lane);
                supmask |= s ? (1u << i) : 0u;
            }

            // greedy resolve via ballots (cost ~per-keep, not per-candidate)
            unsigned alive = __ballot_sync(FULL, valid && !sup);
            while (alive && cnt < DETK) {
                int i = __ffs(alive) - 1;
                if (lane == i) {
                    sm.kbox[cnt]    = bx;
                    sm.karea[cnt]   = ar;
                    sm.keepkey[cnt] = k32;
                }
                unsigned dead = __ballot_sync(FULL, (supmask >> i) & 1u);
                alive &= ~dead & ~(1u << i);
                cnt++;
            }
            __syncwarp();   // make keep-list writes visible for next window
        }
        if (lane == 0) sm.cnt = cnt;
    }
    __syncthreads();

    // ---- Phase 4: outputs [boxes 3200 | scores 800 | classes 800 | valid 800] ----
    if (tid < DETK) {
        int k = tid;
        float4 ob = make_float4(0.f, 0.f, 0.f, 0.f);
        float os = 0.f, oc = 0.f, ov = 0.f;
        if (k < sm.cnt) {
            ob = sm.kbox[k];
            os = s2f(sm.keepkey[k]);
            oc = 1.0f;
            ov = 1.0f;
        }
        float* obp = out + ((size_t)b * DETK + k) * 4;
        obp[0] = ob.x; obp[1] = ob.y; obp[2] = ob.z; obp[3] = ob.w;
        const int SB = BN * DETK * 4;   // 3200
        const int SC = BN * DETK;       // 800
        out[SB +          b * DETK + k] = os;
        out[SB + SC +     b * DETK + k] = oc;
        out[SB + 2 * SC + b * DETK + k] = ov;
    }
}

extern "C" void kernel_launch(void* const* d_in, const int* in_sizes, int n_in,
                              void* d_out, int out_size) {
    const float* clss  = (const float*)d_in[0];
    const float* regs  = (const float*)d_in[1];
    const float* qlts  = (const float*)d_in[2];
    const float* props = (const float*)d_in[3];
    float* out = (float*)d_out;

    size_t smem = sizeof(Smem);
    cudaFuncSetAttribute(seas_postprocess_kernel,
                         cudaFuncAttributeMaxDynamicSharedMemorySize, (int)smem);
    seas_postprocess_kernel<<<BN, NT, smem>>>(clss, regs, qlts, props, out);
}